// round 16
// baseline (speedup 1.0000x reference)
#include <cuda_runtime.h>

// PMLoss: PoseCNN point-matching loss, single fused kernel.
// Heavy blocks: 8 warps split q 8-ways (128 q each), each lane owns 8 p
// -> 8x LDS amortization, 2 warps/SMSP latency overlap; smem min-combine.

#define NB        128
#define NC        22
#define NP        1024
#define NPAIR     (NP / 2)
#define NCHUNK    4
#define NTHREADS  256                  // 8 warps; heavy: 32 lanes x 8 p = 256 p
#define NBLOCKS   (NB * NCHUNK)
#define BIGF      3.402823e38f

#define FXSCALE   1099511627776.0      // 2^40 fixed-point scale

__device__ unsigned long long g_acc;     // zero at load; last block resets
__device__ unsigned int       g_count;   // zero at load; last block resets

__device__ __forceinline__ unsigned long long pack2(float lo, float hi) {
    unsigned long long r;
    asm("mov.b64 %0, {%1, %2};" : "=l"(r) : "f"(lo), "f"(hi));
    return r;
}
__device__ __forceinline__ void unpack2(unsigned long long v, float& lo, float& hi) {
    asm("mov.b64 {%0, %1}, %2;" : "=f"(lo), "=f"(hi) : "l"(v));
}
// Packed dual fp32 FMA (FFMA2) — only reachable via PTX fma.rn.f32x2.
__device__ __forceinline__ unsigned long long fma2(
    unsigned long long a, unsigned long long b, unsigned long long c) {
    unsigned long long d;
    asm("fma.rn.f32x2 %0, %1, %2, %3;" : "=l"(d) : "l"(a), "l"(b), "l"(c));
    return d;
}

__device__ __forceinline__ float warp_reduce_sum(float v) {
    v += __shfl_xor_sync(0xffffffffu, v, 16);
    v += __shfl_xor_sync(0xffffffffu, v, 8);
    v += __shfl_xor_sync(0xffffffffu, v, 4);
    v += __shfl_xor_sync(0xffffffffu, v, 2);
    v += __shfl_xor_sync(0xffffffffu, v, 1);
    return v;
}

__global__ __launch_bounds__(NTHREADS, 3) void pm_loss_main(
    const float* __restrict__ pred, const float* __restrict__ tgt,
    const float* __restrict__ wgt,  const float* __restrict__ points,
    const float* __restrict__ sym,  float* __restrict__ out)
{
    const int chunk = blockIdx.x;    // consecutive bids = chunks of same ROI
    const int b     = blockIdx.y;
    const int tid   = threadIdx.x;
    const int lane  = tid & 31;
    const int wrp   = tid >> 5;      // 0..7

    __shared__ ulonglong2 s_xy[NPAIR];        // packed (-2x,-2y)   (8 KB)
    __shared__ ulonglong2 s_zw[NPAIR];        // packed (-2z, n)    (8 KB)
    __shared__ float s_part[8][NTHREADS];     // per-warp partial mins (8 KB)
    __shared__ float s_cp[NTHREADS];          // |pp|^2 per p       (1 KB)
    __shared__ float s_R[18];                 // Rp[0..8], Rt[9..17]
    __shared__ int   s_cls;
    __shared__ float s_issym;
    __shared__ float s_warp[NTHREADS / 32];

    if (tid == 0) {
        // argmax over weight[b, c, 0] (first-max, matching jnp.argmax)
        const float* w = wgt + b * 4 * NC;
        int cls = 0; float best = w[0];
        #pragma unroll
        for (int c = 1; c < NC; c++) {
            float v = w[4 * c];
            if (v > best) { best = v; cls = c; }
        }
        s_cls   = cls;
        s_issym = sym[cls];

        // predicted quaternion (normalized) -> Rp
        const float* qp = pred + b * 4 * NC + 4 * cls;
        float qw = qp[0], qx = qp[1], qy = qp[2], qz = qp[3];
        float inv = rsqrtf(qw*qw + qx*qx + qy*qy + qz*qz);
        qw *= inv; qx *= inv; qy *= inv; qz *= inv;
        s_R[0] = 1.f - 2.f*(qy*qy + qz*qz); s_R[1] = 2.f*(qx*qy - qw*qz); s_R[2] = 2.f*(qx*qz + qw*qy);
        s_R[3] = 2.f*(qx*qy + qw*qz); s_R[4] = 1.f - 2.f*(qx*qx + qz*qz); s_R[5] = 2.f*(qy*qz - qw*qx);
        s_R[6] = 2.f*(qx*qz - qw*qy); s_R[7] = 2.f*(qy*qz + qw*qx); s_R[8] = 1.f - 2.f*(qx*qx + qy*qy);

        // target quaternion (already unit-norm) -> Rt
        const float* qt = tgt + b * 4 * NC + 4 * cls;
        qw = qt[0]; qx = qt[1]; qy = qt[2]; qz = qt[3];
        s_R[ 9] = 1.f - 2.f*(qy*qy + qz*qz); s_R[10] = 2.f*(qx*qy - qw*qz); s_R[11] = 2.f*(qx*qz + qw*qy);
        s_R[12] = 2.f*(qx*qy + qw*qz); s_R[13] = 1.f - 2.f*(qx*qx + qz*qz); s_R[14] = 2.f*(qy*qz - qw*qx);
        s_R[15] = 2.f*(qx*qz - qw*qy); s_R[16] = 2.f*(qy*qz + qw*qx); s_R[17] = 1.f - 2.f*(qx*qx + qy*qy);
    }
    __syncthreads();

    const int  cls  = s_cls;
    const bool symb = (s_issym > 0.f);       // block-uniform
    const float* pts = points + (size_t)cls * NP * 3;
    const int pbase = chunk * NTHREADS;      // 256 p per block

    float acc;

    if (symb) {
        // ── Build packed target-rotated table (all 1024 q): 2 iters/thread ──
        {
            const float r0 = s_R[ 9], r1 = s_R[10], r2 = s_R[11];
            const float r3 = s_R[12], r4 = s_R[13], r5 = s_R[14];
            const float r6 = s_R[15], r7 = s_R[16], r8 = s_R[17];
            for (int i = tid; i < NPAIR; i += NTHREADS) {
                int q0 = 2 * i;
                float x0 = pts[3*q0+0], y0 = pts[3*q0+1], z0 = pts[3*q0+2];
                float x1 = pts[3*q0+3], y1 = pts[3*q0+4], z1 = pts[3*q0+5];
                float tx0 = r0*x0 + r1*y0 + r2*z0, tx1 = r0*x1 + r1*y1 + r2*z1;
                float ty0 = r3*x0 + r4*y0 + r5*z0, ty1 = r3*x1 + r4*y1 + r5*z1;
                float tz0 = r6*x0 + r7*y0 + r8*z0, tz1 = r6*x1 + r7*y1 + r8*z1;
                float n0 = tx0*tx0 + ty0*ty0 + tz0*tz0;
                float n1 = tx1*tx1 + ty1*ty1 + tz1*tz1;
                ulonglong2 xy, zw;
                xy.x = pack2(-2.f*tx0, -2.f*tx1);
                xy.y = pack2(-2.f*ty0, -2.f*ty1);
                zw.x = pack2(-2.f*tz0, -2.f*tz1);
                zw.y = pack2(n0, n1);
                s_xy[i] = xy;
                s_zw[i] = zw;
            }
        }

        // ── Each lane owns 8 p's: p_j = pbase + lane + 32*j ──
        unsigned long long px2[8], py2[8], pz2[8];
        {
            const float r0 = s_R[0], r1 = s_R[1], r2 = s_R[2];
            const float r3 = s_R[3], r4 = s_R[4], r5 = s_R[5];
            const float r6 = s_R[6], r7 = s_R[7], r8 = s_R[8];
            #pragma unroll
            for (int j = 0; j < 8; j++) {
                int p = pbase + lane + 32 * j;
                float x = pts[3*p], y = pts[3*p+1], z = pts[3*p+2];
                float ppx = r0*x + r1*y + r2*z;
                float ppy = r3*x + r4*y + r5*z;
                float ppz = r6*x + r7*y + r8*z;
                px2[j] = pack2(ppx, ppx);
                py2[j] = pack2(ppy, ppy);
                pz2[j] = pack2(ppz, ppz);
                if (wrp == 0) s_cp[lane + 32 * j] = ppx*ppx + ppy*ppy + ppz*ppz;
            }
        }
        __syncthreads();

        // ── Warp w scans pairs [w*64, w*64+64) for its 256 p's ──
        float m0 = BIGF, m1 = BIGF, m2 = BIGF, m3 = BIGF;
        float m4 = BIGF, m5 = BIGF, m6 = BIGF, m7 = BIGF;
        const int i0 = wrp * (NPAIR / 8);
        #pragma unroll 2
        for (int i = i0; i < i0 + NPAIR / 8; i++) {
            ulonglong2 xy = s_xy[i], zw = s_zw[i];

            unsigned long long v0 = fma2(pz2[0], zw.x, fma2(py2[0], xy.y, fma2(px2[0], xy.x, zw.y)));
            unsigned long long v1 = fma2(pz2[1], zw.x, fma2(py2[1], xy.y, fma2(px2[1], xy.x, zw.y)));
            unsigned long long v2 = fma2(pz2[2], zw.x, fma2(py2[2], xy.y, fma2(px2[2], xy.x, zw.y)));
            unsigned long long v3 = fma2(pz2[3], zw.x, fma2(py2[3], xy.y, fma2(px2[3], xy.x, zw.y)));
            unsigned long long v4 = fma2(pz2[4], zw.x, fma2(py2[4], xy.y, fma2(px2[4], xy.x, zw.y)));
            unsigned long long v5 = fma2(pz2[5], zw.x, fma2(py2[5], xy.y, fma2(px2[5], xy.x, zw.y)));
            unsigned long long v6 = fma2(pz2[6], zw.x, fma2(py2[6], xy.y, fma2(px2[6], xy.x, zw.y)));
            unsigned long long v7 = fma2(pz2[7], zw.x, fma2(py2[7], xy.y, fma2(px2[7], xy.x, zw.y)));

            float a, bf;
            unpack2(v0, a, bf); m0 = fminf(m0, fminf(a, bf));
            unpack2(v1, a, bf); m1 = fminf(m1, fminf(a, bf));
            unpack2(v2, a, bf); m2 = fminf(m2, fminf(a, bf));
            unpack2(v3, a, bf); m3 = fminf(m3, fminf(a, bf));
            unpack2(v4, a, bf); m4 = fminf(m4, fminf(a, bf));
            unpack2(v5, a, bf); m5 = fminf(m5, fminf(a, bf));
            unpack2(v6, a, bf); m6 = fminf(m6, fminf(a, bf));
            unpack2(v7, a, bf); m7 = fminf(m7, fminf(a, bf));
        }
        s_part[wrp][lane +   0] = m0;
        s_part[wrp][lane +  32] = m1;
        s_part[wrp][lane +  64] = m2;
        s_part[wrp][lane +  96] = m3;
        s_part[wrp][lane + 128] = m4;
        s_part[wrp][lane + 160] = m5;
        s_part[wrp][lane + 192] = m6;
        s_part[wrp][lane + 224] = m7;
        __syncthreads();

        // ── Combine: thread tid owns p-index tid (0..255) ──
        float mn = fminf(fminf(fminf(s_part[0][tid], s_part[1][tid]),
                               fminf(s_part[2][tid], s_part[3][tid])),
                         fminf(fminf(s_part[4][tid], s_part[5][tid]),
                               fminf(s_part[6][tid], s_part[7][tid])));
        acc = s_cp[tid] + mn;
    } else {
        // Non-symmetric: thread tid owns p = pbase + tid; |pp - pt|^2
        const int p = pbase + tid;
        const float x = pts[3*p], y = pts[3*p+1], z = pts[3*p+2];
        const float a0 = s_R[0], a1 = s_R[1], a2 = s_R[2];
        const float a3 = s_R[3], a4 = s_R[4], a5 = s_R[5];
        const float a6 = s_R[6], a7 = s_R[7], a8 = s_R[8];
        const float t0 = s_R[ 9], t1 = s_R[10], t2 = s_R[11];
        const float t3 = s_R[12], t4 = s_R[13], t5 = s_R[14];
        const float t6 = s_R[15], t7 = s_R[16], t8 = s_R[17];
        float ppx = a0*x + a1*y + a2*z;
        float ppy = a3*x + a4*y + a5*z;
        float ppz = a6*x + a7*y + a8*z;
        float tx  = t0*x + t1*y + t2*z;
        float ty  = t3*x + t4*y + t5*z;
        float tz  = t6*x + t7*y + t8*z;
        float dx = ppx - tx, dy = ppy - ty, dz = ppz - tz;
        acc = dx*dx + dy*dy + dz*dz;
    }

    // Block reduction (8 warps)
    float s = warp_reduce_sum(acc);
    if ((tid & 31) == 0) s_warp[tid >> 5] = s;
    __syncthreads();
    if (tid == 0) {
        float v = s_warp[0];
        #pragma unroll
        for (int wdx = 1; wdx < NTHREADS / 32; wdx++) v += s_warp[wdx];

        // Deterministic fixed-point accumulation
        long long fx = __double2ll_rn((double)v * FXSCALE);
        atomicAdd(&g_acc, (unsigned long long)fx);
        __threadfence();
        unsigned int ticket = atomicAdd(&g_count, 1u);
        if (ticket == NBLOCKS - 1) {
            long long total = (long long)atomicAdd(&g_acc, 0ULL);
            out[0] = (float)((double)total / FXSCALE
                             * (1.0 / (2.0 * (double)NB * (double)NP)));
            g_acc   = 0ULL;
            __threadfence();
            g_count = 0u;
        }
    }
}

extern "C" void kernel_launch(void* const* d_in, const int* in_sizes, int n_in,
                              void* d_out, int out_size) {
    const float* pred = (const float*)d_in[0];
    const float* tgt  = (const float*)d_in[1];
    const float* wgt  = (const float*)d_in[2];
    const float* pts  = (const float*)d_in[3];
    const float* sym  = (const float*)d_in[4];

    dim3 grid(NCHUNK, NB);
    pm_loss_main<<<grid, NTHREADS>>>(pred, tgt, wgt, pts, sym, (float*)d_out);
}

// round 17
// speedup vs baseline: 1.2280x; 1.2280x over previous
#include <cuda_runtime.h>

// PMLoss: PoseCNN point-matching loss, single fused kernel.
// Heavy (symmetric) blocks: 4 warps split the q-range (256 q each), each lane
// carries 4 p-points; scan body processes 4 pair-entries (8 batched LDS.128).

#define NB        128
#define NC        22
#define NP        1024
#define NPAIR     (NP / 2)
#define NCHUNK    8
#define NTHREADS  128                  // 4 warps; heavy: 32 lanes x 4 p = 128 p
#define NBLOCKS   (NB * NCHUNK)
#define BIGF      3.402823e38f

#define FXSCALE   1099511627776.0      // 2^40 fixed-point scale

__device__ unsigned long long g_acc;     // zero at load; last block resets
__device__ unsigned int       g_count;   // zero at load; last block resets

__device__ __forceinline__ unsigned long long pack2(float lo, float hi) {
    unsigned long long r;
    asm("mov.b64 %0, {%1, %2};" : "=l"(r) : "f"(lo), "f"(hi));
    return r;
}
__device__ __forceinline__ void unpack2(unsigned long long v, float& lo, float& hi) {
    asm("mov.b64 {%0, %1}, %2;" : "=f"(lo), "=f"(hi) : "l"(v));
}
// Packed dual fp32 FMA (FFMA2) — only reachable via PTX fma.rn.f32x2.
__device__ __forceinline__ unsigned long long fma2(
    unsigned long long a, unsigned long long b, unsigned long long c) {
    unsigned long long d;
    asm("fma.rn.f32x2 %0, %1, %2, %3;" : "=l"(d) : "l"(a), "l"(b), "l"(c));
    return d;
}

__device__ __forceinline__ float warp_reduce_sum(float v) {
    v += __shfl_xor_sync(0xffffffffu, v, 16);
    v += __shfl_xor_sync(0xffffffffu, v, 8);
    v += __shfl_xor_sync(0xffffffffu, v, 4);
    v += __shfl_xor_sync(0xffffffffu, v, 2);
    v += __shfl_xor_sync(0xffffffffu, v, 1);
    return v;
}

__global__ __launch_bounds__(NTHREADS, 6) void pm_loss_main(
    const float* __restrict__ pred, const float* __restrict__ tgt,
    const float* __restrict__ wgt,  const float* __restrict__ points,
    const float* __restrict__ sym,  float* __restrict__ out)
{
    const int chunk = blockIdx.x;    // consecutive bids = chunks of same ROI
    const int b     = blockIdx.y;    // -> heavy ROI spreads across 8 SMs
    const int tid   = threadIdx.x;
    const int lane  = tid & 31;
    const int wrp   = tid >> 5;

    __shared__ ulonglong2 s_xy[NPAIR];        // packed (-2x,-2y)   (8 KB)
    __shared__ ulonglong2 s_zw[NPAIR];        // packed (-2z, n)    (8 KB)
    __shared__ float s_part[4][NTHREADS];     // per-warp partial mins (2 KB)
    __shared__ float s_cp[NTHREADS];          // |pp|^2 per p       (0.5 KB)
    __shared__ float s_R[18];                 // Rp[0..8], Rt[9..17]
    __shared__ int   s_cls;
    __shared__ float s_issym;
    __shared__ float s_warp[NTHREADS / 32];

    if (tid == 0) {
        // argmax over weight[b, c, 0] (first-max, matching jnp.argmax)
        const float* w = wgt + b * 4 * NC;
        int cls = 0; float best = w[0];
        #pragma unroll
        for (int c = 1; c < NC; c++) {
            float v = w[4 * c];
            if (v > best) { best = v; cls = c; }
        }
        s_cls   = cls;
        s_issym = sym[cls];

        // predicted quaternion (normalized) -> Rp
        const float* qp = pred + b * 4 * NC + 4 * cls;
        float qw = qp[0], qx = qp[1], qy = qp[2], qz = qp[3];
        float inv = rsqrtf(qw*qw + qx*qx + qy*qy + qz*qz);
        qw *= inv; qx *= inv; qy *= inv; qz *= inv;
        s_R[0] = 1.f - 2.f*(qy*qy + qz*qz); s_R[1] = 2.f*(qx*qy - qw*qz); s_R[2] = 2.f*(qx*qz + qw*qy);
        s_R[3] = 2.f*(qx*qy + qw*qz); s_R[4] = 1.f - 2.f*(qx*qx + qz*qz); s_R[5] = 2.f*(qy*qz - qw*qx);
        s_R[6] = 2.f*(qx*qz - qw*qy); s_R[7] = 2.f*(qy*qz + qw*qx); s_R[8] = 1.f - 2.f*(qx*qx + qy*qy);

        // target quaternion (already unit-norm) -> Rt
        const float* qt = tgt + b * 4 * NC + 4 * cls;
        qw = qt[0]; qx = qt[1]; qy = qt[2]; qz = qt[3];
        s_R[ 9] = 1.f - 2.f*(qy*qy + qz*qz); s_R[10] = 2.f*(qx*qy - qw*qz); s_R[11] = 2.f*(qx*qz + qw*qy);
        s_R[12] = 2.f*(qx*qy + qw*qz); s_R[13] = 1.f - 2.f*(qx*qx + qz*qz); s_R[14] = 2.f*(qy*qz - qw*qx);
        s_R[15] = 2.f*(qx*qz - qw*qy); s_R[16] = 2.f*(qy*qz + qw*qx); s_R[17] = 1.f - 2.f*(qx*qx + qy*qy);
    }
    __syncthreads();

    const int  cls  = s_cls;
    const bool symb = (s_issym > 0.f);       // block-uniform
    const float* pts = points + (size_t)cls * NP * 3;
    const int pbase = chunk * NTHREADS;

    float acc;   // defined for tid's own p below

    if (symb) {
        // ── Build packed target-rotated table (all 1024 q) ──
        {
            const float r0 = s_R[ 9], r1 = s_R[10], r2 = s_R[11];
            const float r3 = s_R[12], r4 = s_R[13], r5 = s_R[14];
            const float r6 = s_R[15], r7 = s_R[16], r8 = s_R[17];
            for (int i = tid; i < NPAIR; i += NTHREADS) {
                int q0 = 2 * i;
                float x0 = pts[3*q0+0], y0 = pts[3*q0+1], z0 = pts[3*q0+2];
                float x1 = pts[3*q0+3], y1 = pts[3*q0+4], z1 = pts[3*q0+5];
                float tx0 = r0*x0 + r1*y0 + r2*z0, tx1 = r0*x1 + r1*y1 + r2*z1;
                float ty0 = r3*x0 + r4*y0 + r5*z0, ty1 = r3*x1 + r4*y1 + r5*z1;
                float tz0 = r6*x0 + r7*y0 + r8*z0, tz1 = r6*x1 + r7*y1 + r8*z1;
                float n0 = tx0*tx0 + ty0*ty0 + tz0*tz0;
                float n1 = tx1*tx1 + ty1*ty1 + tz1*tz1;
                ulonglong2 xy, zw;
                xy.x = pack2(-2.f*tx0, -2.f*tx1);
                xy.y = pack2(-2.f*ty0, -2.f*ty1);
                zw.x = pack2(-2.f*tz0, -2.f*tz1);
                zw.y = pack2(n0, n1);
                s_xy[i] = xy;
                s_zw[i] = zw;
            }
        }

        // ── Each lane owns 4 p's: p_j = pbase + lane + 32*j ──
        unsigned long long px2[4], py2[4], pz2[4];
        {
            const float r0 = s_R[0], r1 = s_R[1], r2 = s_R[2];
            const float r3 = s_R[3], r4 = s_R[4], r5 = s_R[5];
            const float r6 = s_R[6], r7 = s_R[7], r8 = s_R[8];
            #pragma unroll
            for (int j = 0; j < 4; j++) {
                int p = pbase + lane + 32 * j;
                float x = pts[3*p], y = pts[3*p+1], z = pts[3*p+2];
                float ppx = r0*x + r1*y + r2*z;
                float ppy = r3*x + r4*y + r5*z;
                float ppz = r6*x + r7*y + r8*z;
                px2[j] = pack2(ppx, ppx);
                py2[j] = pack2(ppy, ppy);
                pz2[j] = pack2(ppz, ppz);
                if (wrp == 0) s_cp[lane + 32 * j] = ppx*ppx + ppy*ppy + ppz*ppz;
            }
        }
        __syncthreads();

        // ── Warp w scans pairs [w*128, w*128+128): 4 entries per body,
        //    8 LDS.128 batched up front (one load-stall per ~60 issues) ──
        float m0 = BIGF, m1 = BIGF, m2 = BIGF, m3 = BIGF;
        const int i0 = wrp * (NPAIR / 4);
        #pragma unroll 1
        for (int i = i0; i < i0 + NPAIR / 4; i += 4) {
            ulonglong2 xyA = s_xy[i],   zwA = s_zw[i];
            ulonglong2 xyB = s_xy[i+1], zwB = s_zw[i+1];
            ulonglong2 xyC = s_xy[i+2], zwC = s_zw[i+2];
            ulonglong2 xyD = s_xy[i+3], zwD = s_zw[i+3];

            unsigned long long vA0 = fma2(pz2[0], zwA.x, fma2(py2[0], xyA.y, fma2(px2[0], xyA.x, zwA.y)));
            unsigned long long vA1 = fma2(pz2[1], zwA.x, fma2(py2[1], xyA.y, fma2(px2[1], xyA.x, zwA.y)));
            unsigned long long vA2 = fma2(pz2[2], zwA.x, fma2(py2[2], xyA.y, fma2(px2[2], xyA.x, zwA.y)));
            unsigned long long vA3 = fma2(pz2[3], zwA.x, fma2(py2[3], xyA.y, fma2(px2[3], xyA.x, zwA.y)));
            unsigned long long vB0 = fma2(pz2[0], zwB.x, fma2(py2[0], xyB.y, fma2(px2[0], xyB.x, zwB.y)));
            unsigned long long vB1 = fma2(pz2[1], zwB.x, fma2(py2[1], xyB.y, fma2(px2[1], xyB.x, zwB.y)));
            unsigned long long vB2 = fma2(pz2[2], zwB.x, fma2(py2[2], xyB.y, fma2(px2[2], xyB.x, zwB.y)));
            unsigned long long vB3 = fma2(pz2[3], zwB.x, fma2(py2[3], xyB.y, fma2(px2[3], xyB.x, zwB.y)));
            unsigned long long vC0 = fma2(pz2[0], zwC.x, fma2(py2[0], xyC.y, fma2(px2[0], xyC.x, zwC.y)));
            unsigned long long vC1 = fma2(pz2[1], zwC.x, fma2(py2[1], xyC.y, fma2(px2[1], xyC.x, zwC.y)));
            unsigned long long vC2 = fma2(pz2[2], zwC.x, fma2(py2[2], xyC.y, fma2(px2[2], xyC.x, zwC.y)));
            unsigned long long vC3 = fma2(pz2[3], zwC.x, fma2(py2[3], xyC.y, fma2(px2[3], xyC.x, zwC.y)));
            unsigned long long vD0 = fma2(pz2[0], zwD.x, fma2(py2[0], xyD.y, fma2(px2[0], xyD.x, zwD.y)));
            unsigned long long vD1 = fma2(pz2[1], zwD.x, fma2(py2[1], xyD.y, fma2(px2[1], xyD.x, zwD.y)));
            unsigned long long vD2 = fma2(pz2[2], zwD.x, fma2(py2[2], xyD.y, fma2(px2[2], xyD.x, zwD.y)));
            unsigned long long vD3 = fma2(pz2[3], zwD.x, fma2(py2[3], xyD.y, fma2(px2[3], xyD.x, zwD.y)));

            float a, bf;
            unpack2(vA0, a, bf); m0 = fminf(m0, fminf(a, bf));
            unpack2(vA1, a, bf); m1 = fminf(m1, fminf(a, bf));
            unpack2(vA2, a, bf); m2 = fminf(m2, fminf(a, bf));
            unpack2(vA3, a, bf); m3 = fminf(m3, fminf(a, bf));
            unpack2(vB0, a, bf); m0 = fminf(m0, fminf(a, bf));
            unpack2(vB1, a, bf); m1 = fminf(m1, fminf(a, bf));
            unpack2(vB2, a, bf); m2 = fminf(m2, fminf(a, bf));
            unpack2(vB3, a, bf); m3 = fminf(m3, fminf(a, bf));
            unpack2(vC0, a, bf); m0 = fminf(m0, fminf(a, bf));
            unpack2(vC1, a, bf); m1 = fminf(m1, fminf(a, bf));
            unpack2(vC2, a, bf); m2 = fminf(m2, fminf(a, bf));
            unpack2(vC3, a, bf); m3 = fminf(m3, fminf(a, bf));
            unpack2(vD0, a, bf); m0 = fminf(m0, fminf(a, bf));
            unpack2(vD1, a, bf); m1 = fminf(m1, fminf(a, bf));
            unpack2(vD2, a, bf); m2 = fminf(m2, fminf(a, bf));
            unpack2(vD3, a, bf); m3 = fminf(m3, fminf(a, bf));
        }
        s_part[wrp][lane +  0] = m0;
        s_part[wrp][lane + 32] = m1;
        s_part[wrp][lane + 64] = m2;
        s_part[wrp][lane + 96] = m3;
        __syncthreads();

        // ── Combine: thread tid owns p-index tid ──
        float mn = fminf(fminf(s_part[0][tid], s_part[1][tid]),
                         fminf(s_part[2][tid], s_part[3][tid]));
        acc = s_cp[tid] + mn;
    } else {
        // Non-symmetric: thread tid owns p = pbase + tid; |pp - pt|^2
        const int p = pbase + tid;
        const float x = pts[3*p], y = pts[3*p+1], z = pts[3*p+2];
        const float a0 = s_R[0], a1 = s_R[1], a2 = s_R[2];
        const float a3 = s_R[3], a4 = s_R[4], a5 = s_R[5];
        const float a6 = s_R[6], a7 = s_R[7], a8 = s_R[8];
        const float t0 = s_R[ 9], t1 = s_R[10], t2 = s_R[11];
        const float t3 = s_R[12], t4 = s_R[13], t5 = s_R[14];
        const float t6 = s_R[15], t7 = s_R[16], t8 = s_R[17];
        float ppx = a0*x + a1*y + a2*z;
        float ppy = a3*x + a4*y + a5*z;
        float ppz = a6*x + a7*y + a8*z;
        float tx  = t0*x + t1*y + t2*z;
        float ty  = t3*x + t4*y + t5*z;
        float tz  = t6*x + t7*y + t8*z;
        float dx = ppx - tx, dy = ppy - ty, dz = ppz - tz;
        acc = dx*dx + dy*dy + dz*dz;
    }

    // Block reduction
    float s = warp_reduce_sum(acc);
    if ((tid & 31) == 0) s_warp[tid >> 5] = s;
    __syncthreads();
    if (tid == 0) {
        float v = s_warp[0];
        #pragma unroll
        for (int wdx = 1; wdx < NTHREADS / 32; wdx++) v += s_warp[wdx];

        // Deterministic fixed-point accumulation
        long long fx = __double2ll_rn((double)v * FXSCALE);
        atomicAdd(&g_acc, (unsigned long long)fx);
        __threadfence();
        unsigned int ticket = atomicAdd(&g_count, 1u);
        if (ticket == NBLOCKS - 1) {
            long long total = (long long)atomicAdd(&g_acc, 0ULL);
            out[0] = (float)((double)total / FXSCALE
                             * (1.0 / (2.0 * (double)NB * (double)NP)));
            g_acc   = 0ULL;
            __threadfence();
            g_count = 0u;
        }
    }
}

extern "C" void kernel_launch(void* const* d_in, const int* in_sizes, int n_in,
                              void* d_out, int out_size) {
    const float* pred = (const float*)d_in[0];
    const float* tgt  = (const float*)d_in[1];
    const float* wgt  = (const float*)d_in[2];
    const float* pts  = (const float*)d_in[3];
    const float* sym  = (const float*)d_in[4];

    dim3 grid(NCHUNK, NB);
    pm_loss_main<<<grid, NTHREADS>>>(pred, tgt, wgt, pts, sym, (float*)d_out);
}